// round 10
// baseline (speedup 1.0000x reference)
#include <cuda_runtime.h>
#include <cuda_bf16.h>
#include <stdint.h>

// BEVPool as a balanced segmented reduction over SORTED ranks_bev.
// R9: feat rows padded 320B -> 384B (3 aligned 128B lines) in a device scratch
// buffer to cut L1 wavefronts per gather; 320-thread blocks for occupancy.
// Each 20-lane group owns a FIXED range of SUB consecutive points; run-length
// segments accumulate in registers; interior segments -> plain store,
// edge segments -> red.global.add.v4.f32 into zero-initialized output.
// NOTE: JAX x64-disabled => rank buffers are int32 on device.

#define C4 20                       // 80 channels / 4
#define PADC4 24                    // padded row: 24 float4 = 384 B
#define NFEAT_ROWS 4224
#define GROUPS 16
#define THREADS (C4 * GROUPS)       // 320
#define SUB 96                      // points per group
#define CHUNK (GROUPS * SUB)        // 1536 points per block

__device__ float4 g_featpad[NFEAT_ROWS * PADC4];   // 1.62 MB scratch

__device__ __forceinline__ void red_add_v4(float4* p, float4 v)
{
    asm volatile("red.global.add.v4.f32 [%0], {%1, %2, %3, %4};"
                 :: "l"(p), "f"(v.x), "f"(v.y), "f"(v.z), "f"(v.w)
                 : "memory");
}

// Fused: zero the output AND build the padded feat table.
__global__ void init_kernel(const float4* __restrict__ feat4,
                            float4* __restrict__ out4,
                            int n4, int nrows)
{
    const int i = blockIdx.x * blockDim.x + threadIdx.x;
    const float4 z = make_float4(0.f, 0.f, 0.f, 0.f);
    if (i < n4) out4[i] = z;
    const int j = i - n4;
    if (j >= 0 && j < nrows * PADC4) {
        const int r = j / PADC4;
        const int c = j - r * PADC4;
        g_featpad[j] = (c < C4) ? __ldg(&feat4[r * C4 + c]) : z;
    }
}

__global__ __launch_bounds__(THREADS)
void bevpool_scan_kernel(const float* __restrict__ depth,
                         const int* __restrict__ ranks_depth,
                         const int* __restrict__ ranks_feat,
                         const int* __restrict__ ranks_bev,
                         float* __restrict__ out,
                         int P)
{
    __shared__ int   s_rf[CHUNK];    // pre-scaled: rf * PADC4
    __shared__ float s_d[CHUNK];
    __shared__ int   s_bev[CHUNK];

    const int base = blockIdx.x * CHUNK;
    const int tid  = threadIdx.x;
    const int n    = min(CHUNK, P - base);
    if (n <= 0) return;

    // ---- stage: coalesced loads + depth gather -> smem ----
    #pragma unroll 2
    for (int j = tid; j < n; j += THREADS) {
        const int idx = base + j;
        const int rd  = __ldg(&ranks_depth[idx]);
        s_rf[j]  = __ldg(&ranks_feat[idx]) * PADC4;
        s_bev[j] = __ldg(&ranks_bev[idx]);
        s_d[j]   = __ldg(&depth[rd]);
    }
    __syncthreads();

    const int y = tid / C4;          // group id
    const int x = tid % C4;          // float4 channel slot

    const int lo = y * SUB;
    const int hi = min(lo + SUB, n);
    if (lo >= n) return;

    const float4* __restrict__ featp = g_featpad;
    float4* __restrict__ out4        = (float4*)out;

    int    cur   = s_bev[lo];
    bool   first = true;             // current segment may extend left of range
    float4 acc   = make_float4(0.f, 0.f, 0.f, 0.f);

    int j = lo;
    for (; j + 4 <= hi; j += 4) {
        const int   r0 = s_rf[j + 0], r1 = s_rf[j + 1];
        const int   r2 = s_rf[j + 2], r3 = s_rf[j + 3];
        const float d0 = s_d[j + 0],  d1 = s_d[j + 1];
        const float d2 = s_d[j + 2],  d3 = s_d[j + 3];
        const int   b0 = s_bev[j + 0], b1 = s_bev[j + 1];
        const int   b2 = s_bev[j + 2], b3 = s_bev[j + 3];

        const float4 v0 = __ldg(&featp[r0 + x]);
        const float4 v1 = __ldg(&featp[r1 + x]);
        const float4 v2 = __ldg(&featp[r2 + x]);
        const float4 v3 = __ldg(&featp[r3 + x]);

        if (b0 != cur) {
            if (first) red_add_v4(&out4[cur * C4 + x], acc);
            else       out4[cur * C4 + x] = acc;
            first = false; acc = make_float4(0.f, 0.f, 0.f, 0.f); cur = b0;
        }
        acc.x = fmaf(d0, v0.x, acc.x); acc.y = fmaf(d0, v0.y, acc.y);
        acc.z = fmaf(d0, v0.z, acc.z); acc.w = fmaf(d0, v0.w, acc.w);

        if (b1 != cur) {
            if (first) red_add_v4(&out4[cur * C4 + x], acc);
            else       out4[cur * C4 + x] = acc;
            first = false; acc = make_float4(0.f, 0.f, 0.f, 0.f); cur = b1;
        }
        acc.x = fmaf(d1, v1.x, acc.x); acc.y = fmaf(d1, v1.y, acc.y);
        acc.z = fmaf(d1, v1.z, acc.z); acc.w = fmaf(d1, v1.w, acc.w);

        if (b2 != cur) {
            if (first) red_add_v4(&out4[cur * C4 + x], acc);
            else       out4[cur * C4 + x] = acc;
            first = false; acc = make_float4(0.f, 0.f, 0.f, 0.f); cur = b2;
        }
        acc.x = fmaf(d2, v2.x, acc.x); acc.y = fmaf(d2, v2.y, acc.y);
        acc.z = fmaf(d2, v2.z, acc.z); acc.w = fmaf(d2, v2.w, acc.w);

        if (b3 != cur) {
            if (first) red_add_v4(&out4[cur * C4 + x], acc);
            else       out4[cur * C4 + x] = acc;
            first = false; acc = make_float4(0.f, 0.f, 0.f, 0.f); cur = b3;
        }
        acc.x = fmaf(d3, v3.x, acc.x); acc.y = fmaf(d3, v3.y, acc.y);
        acc.z = fmaf(d3, v3.z, acc.z); acc.w = fmaf(d3, v3.w, acc.w);
    }
    for (; j < hi; j++) {
        const int   r = s_rf[j];
        const float d = s_d[j];
        const int   b = s_bev[j];
        const float4 v = __ldg(&featp[r + x]);
        if (b != cur) {
            if (first) red_add_v4(&out4[cur * C4 + x], acc);
            else       out4[cur * C4 + x] = acc;
            first = false; acc = make_float4(0.f, 0.f, 0.f, 0.f); cur = b;
        }
        acc.x = fmaf(d, v.x, acc.x); acc.y = fmaf(d, v.y, acc.y);
        acc.z = fmaf(d, v.z, acc.z); acc.w = fmaf(d, v.w, acc.w);
    }

    // final segment may extend past the range edge -> always atomic
    red_add_v4(&out4[cur * C4 + x], acc);
}

extern "C" void kernel_launch(void* const* d_in, const int* in_sizes, int n_in,
                              void* d_out, int out_size)
{
    const float* depth       = (const float*)d_in[0];
    const float* feat        = (const float*)d_in[1];
    const int*   ranks_depth = (const int*)d_in[2];
    const int*   ranks_feat  = (const int*)d_in[3];
    const int*   ranks_bev   = (const int*)d_in[4];
    // d_in[5] interval_starts, d_in[6] interval_lengths, d_in[7] total_bev: unused

    float* out = (float*)d_out;

    const int P     = in_sizes[2];          // 1,500,000
    const int n4    = out_size / 4;         // 800,000 float4
    const int nrows = in_sizes[1] / 80;     // 4224

    const int init_threads = n4 + nrows * PADC4;
    init_kernel<<<(init_threads + 255) / 256, 256>>>(
        (const float4*)feat, (float4*)out, n4, nrows);

    const int grid = (P + CHUNK - 1) / CHUNK;
    bevpool_scan_kernel<<<grid, THREADS>>>(depth, ranks_depth,
                                           ranks_feat, ranks_bev, out, P);
}